// round 17
// baseline (speedup 1.0000x reference)
#include <cuda_runtime.h>

// exp(Q*t) for 2,097,152 independent 4x4 fp32 matrices.  FINAL (R17).
// Core: packed f32x2 arithmetic (fma.rn.f32x2 -- 2x fp32/slot, PTX-only),
// degree-8 Paterson-Stockmeyer Taylor at theta=1 (4 matmuls, blocks fused
// into accumulator inits), warp-uniform scaling-and-squaring (warp-max s,
// exponent-field 2^-s, MUFU-free), ping-pong squaring, streaming cache
// hints, TPB=64 fine-grain CTAs. launch_bounds(64,18): ptxas already
// achieves 56 regs (R16-measured, no spills); 18 CTAs/SM = 36-warp ceiling.

#define SEQ_SHIFT 15
#define NMAT (64 * 32768)
#define TPB 64

typedef unsigned long long u64;

__device__ __forceinline__ u64 pack2(float lo, float hi) {
    u64 r; asm("mov.b64 %0, {%1, %2};" : "=l"(r) : "f"(lo), "f"(hi)); return r;
}
__device__ __forceinline__ void unpack2(u64 v, float& lo, float& hi) {
    asm("mov.b64 {%0, %1}, %2;" : "=f"(lo), "=f"(hi) : "l"(v));
}
__device__ __forceinline__ u64 fma2(u64 a, u64 b, u64 c) {
    u64 d; asm("fma.rn.f32x2 %0, %1, %2, %3;" : "=l"(d) : "l"(a), "l"(b), "l"(c)); return d;
}
__device__ __forceinline__ u64 mul2(u64 a, u64 b) {
    u64 d; asm("mul.rn.f32x2 %0, %1, %2;" : "=l"(d) : "l"(a), "l"(b)); return d;
}
__device__ __forceinline__ u64 add2(u64 a, u64 b) {
    u64 d; asm("add.rn.f32x2 %0, %1, %2;" : "=l"(d) : "l"(a), "l"(b)); return d;
}
__device__ __forceinline__ u64 abs2(u64 v) { return v & 0x7FFFFFFF7FFFFFFFull; }

// C = A*B. Ab = 16 broadcast-packed scalars; B, C = 8 packed row-pairs.
__device__ __forceinline__ void mm4p(const u64* __restrict__ Ab,
                                     const u64* __restrict__ B,
                                     u64* __restrict__ C) {
#pragma unroll
    for (int i = 0; i < 4; ++i) {
#pragma unroll
        for (int jp = 0; jp < 2; ++jp) {
            u64 acc = mul2(Ab[i * 4 + 0], B[0 * 2 + jp]);
            acc = fma2(Ab[i * 4 + 1], B[1 * 2 + jp], acc);
            acc = fma2(Ab[i * 4 + 2], B[2 * 2 + jp], acc);
            acc = fma2(Ab[i * 4 + 3], B[3 * 2 + jp], acc);
            C[i * 2 + jp] = acc;
        }
    }
}

// C = A*B + D (additive matrix fused into the accumulator init).
__device__ __forceinline__ void mm4p_acc(const u64* __restrict__ Ab,
                                         const u64* __restrict__ B,
                                         const u64* __restrict__ D,
                                         u64* __restrict__ C) {
#pragma unroll
    for (int i = 0; i < 4; ++i) {
#pragma unroll
        for (int jp = 0; jp < 2; ++jp) {
            u64 acc = fma2(Ab[i * 4 + 0], B[0 * 2 + jp], D[i * 2 + jp]);
            acc = fma2(Ab[i * 4 + 1], B[1 * 2 + jp], acc);
            acc = fma2(Ab[i * 4 + 2], B[2 * 2 + jp], acc);
            acc = fma2(Ab[i * 4 + 3], B[3 * 2 + jp], acc);
            C[i * 2 + jp] = acc;
        }
    }
}

__device__ __forceinline__ void bcast(const u64* __restrict__ Rp,
                                      u64* __restrict__ Rb) {
#pragma unroll
    for (int i = 0; i < 8; ++i) {
        float lo, hi;
        unpack2(Rp[i], lo, hi);
        Rb[2 * i]     = pack2(lo, lo);
        Rb[2 * i + 1] = pack2(hi, hi);
    }
}

// One squaring step: dst = src * src (src in row-pair form).
__device__ __forceinline__ void square_step(const u64* __restrict__ src,
                                            u64* __restrict__ dst) {
    u64 Sb[16];
    bcast(src, Sb);
    mm4p(Sb, src, dst);
}

__global__ __launch_bounds__(TPB, 18)
void expm44_kernel(const float* __restrict__ rate,   // [NMAT, 16]
                   const float* __restrict__ time,   // [64]
                   float* __restrict__ out)          // [NMAT, 16]
{
    const int idx = blockIdx.x * TPB + threadIdx.x;   // grid is exact

    const float t = __ldg(time + (idx >> SEQ_SHIFT));

    // Load 16 floats as 8 packed f32x2 row-pairs (4x LDG.128, streaming).
    const ulonglong2* ap = reinterpret_cast<const ulonglong2*>(rate) + (size_t)idx * 4;
    ulonglong2 l0 = __ldcs(ap + 0);
    ulonglong2 l1 = __ldcs(ap + 1);
    ulonglong2 l2 = __ldcs(ap + 2);
    ulonglong2 l3 = __ldcs(ap + 3);
    u64 Ap[8] = { l0.x, l0.y, l1.x, l1.y, l2.x, l2.y, l3.x, l3.y };

    // inf-norm(A): packed abs + packed row-pair add, then horizontal.
    u64 q0 = add2(abs2(Ap[0]), abs2(Ap[1]));
    u64 q1 = add2(abs2(Ap[2]), abs2(Ap[3]));
    u64 q2 = add2(abs2(Ap[4]), abs2(Ap[5]));
    u64 q3 = add2(abs2(Ap[6]), abs2(Ap[7]));
    float a0, b0, a1, b1, a2, b2, a3, b3;
    unpack2(q0, a0, b0); unpack2(q1, a1, b1);
    unpack2(q2, a2, b2); unpack2(q3, a3, b3);
    const float nrm = fmaxf(fmaxf(a0 + b0, a1 + b1), fmaxf(a2 + b2, a3 + b3)) * t;

    // s ~ ceil(log2(nrm)) via exponent extraction; clamp at 0; warp-max.
    int s = (int)(__float_as_uint(nrm) >> 23) - 126;
    s = max(0, s);
    const unsigned sw = __reduce_max_sync(0xFFFFFFFFu, (unsigned)s);

    // scale = t * 2^-sw (exact exponent-field construction).
    const float scale = t * __uint_as_float((127u - sw) << 23);
    const u64 sc2 = pack2(scale, scale);

    u64 Xp[8];
#pragma unroll
    for (int i = 0; i < 8; ++i) Xp[i] = mul2(Ap[i], sc2);

    u64 Xb[16];
    bcast(Xp, Xb);

    u64 X2[8], X3[8];
    mm4p(Xb, Xp, X2);
    mm4p(Xb, X2, X3);

    u64 X3b[16];
    bcast(X3, X3b);

    const float c2 = 1.0f / 2.0f;
    const float c3 = 1.0f / 6.0f,   c4 = 1.0f / 24.0f,   c5 = 1.0f / 120.0f;
    const float c6 = 1.0f / 720.0f, c7 = 1.0f / 5040.0f, c8 = 1.0f / 40320.0f;

    u64 B0[8], B1[8], B2[8];
#pragma unroll
    for (int i = 0; i < 4; ++i) {
#pragma unroll
        for (int jp = 0; jp < 2; ++jp) {
            const int p = i * 2 + jp;
            const bool dlo = (jp == (i >> 1)) && ((i & 1) == 0);
            const bool dhi = (jp == (i >> 1)) && ((i & 1) == 1);
            const u64 i1  = pack2(dlo ? 1.0f : 0.0f, dhi ? 1.0f : 0.0f);
            const u64 ic3 = pack2(dlo ? c3 : 0.0f,   dhi ? c3 : 0.0f);
            const u64 ic6 = pack2(dlo ? c6 : 0.0f,   dhi ? c6 : 0.0f);
            B0[p] = fma2(X2[p], pack2(c2, c2), add2(Xp[p], i1));
            B1[p] = fma2(X2[p], pack2(c5, c5), fma2(Xp[p], pack2(c4, c4), ic3));
            B2[p] = fma2(X2[p], pack2(c8, c8), fma2(Xp[p], pack2(c7, c7), ic6));
        }
    }

    // Horner in X^3:  T1 = X3*B2 + B1 ;  P = X3*T1 + B0
    u64 T1[8], P[8];
    mm4p_acc(X3b, B2, B1, T1);
    mm4p_acc(X3b, T1, B0, P);

    // Square sw times: ping-pong P <-> C (even/odd unroll, no per-iter copy).
    u64 C[8];
    const unsigned half = sw >> 1;
    for (unsigned q = 0; q < half; ++q) {
        square_step(P, C);
        square_step(C, P);
    }
    if (sw & 1u) {
        square_step(P, C);
#pragma unroll
        for (int i = 0; i < 8; ++i) P[i] = C[i];
    }

    // Store with streaming hint (written once, never re-read).
    ulonglong2* op = reinterpret_cast<ulonglong2*>(out) + (size_t)idx * 4;
    __stcs(op + 0, make_ulonglong2(P[0], P[1]));
    __stcs(op + 1, make_ulonglong2(P[2], P[3]));
    __stcs(op + 2, make_ulonglong2(P[4], P[5]));
    __stcs(op + 3, make_ulonglong2(P[6], P[7]));
}

extern "C" void kernel_launch(void* const* d_in, const int* in_sizes, int n_in,
                              void* d_out, int out_size) {
    const float* rate = (const float*)d_in[0];
    const float* time = (const float*)d_in[1];
    float* out = (float*)d_out;

    expm44_kernel<<<NMAT / TPB, TPB>>>(rate, time, out);
}